// round 4
// baseline (speedup 1.0000x reference)
#include <cuda_runtime.h>
#include <cuda_bf16.h>

// Haar DWT (pywt 'haar', torch-style flipped filters + cross-correlation):
//   a=x[h,w] b=x[h,w+1] c=x[h+1,w] d=x[h+1,w+1]  (zero pad right/bottom)
//   LL=.5(a+b+c+d)  LH=.5(a+b-c-d)  HL=.5(a-b+c-d)  HH=.5(a-b-c+d)
// out[b, 4c+k, h, w]  ->  plane index 4*(b*C+c)+k
//
// R4: warp handles TWO output rows (h, h+1) from THREE input rows (h,h+1,h+2);
// middle row register-reused. 6 front-batched LDG.128 per thread (MLP=6),
// horizontal neighbors via shuffle, all accesses perfect 512B/warp.

#define DWT_W 256
#define DWT_H 256
#define W4    (DWT_W / 4)
#define PLANE4 ((size_t)DWT_H * W4)
#define FULL  0xffffffffu

__device__ __forceinline__ void subbands_store(
    float4* __restrict__ ob, size_t oidx,
    float4 T, float4 B, float tn, float bn)
{
    const float ts0 = T.x + T.y, ts1 = T.y + T.z, ts2 = T.z + T.w, ts3 = T.w + tn;
    const float td0 = T.x - T.y, td1 = T.y - T.z, td2 = T.z - T.w, td3 = T.w - tn;
    const float bs0 = B.x + B.y, bs1 = B.y + B.z, bs2 = B.z + B.w, bs3 = B.w + bn;
    const float bd0 = B.x - B.y, bd1 = B.y - B.z, bd2 = B.z - B.w, bd3 = B.w - bn;

    float4 v;
    v.x = 0.5f * (ts0 + bs0); v.y = 0.5f * (ts1 + bs1);
    v.z = 0.5f * (ts2 + bs2); v.w = 0.5f * (ts3 + bs3);
    __stcs(ob + oidx, v);                                   // LL

    v.x = 0.5f * (ts0 - bs0); v.y = 0.5f * (ts1 - bs1);
    v.z = 0.5f * (ts2 - bs2); v.w = 0.5f * (ts3 - bs3);
    __stcs(ob + PLANE4 + oidx, v);                          // LH

    v.x = 0.5f * (td0 + bd0); v.y = 0.5f * (td1 + bd1);
    v.z = 0.5f * (td2 + bd2); v.w = 0.5f * (td3 + bd3);
    __stcs(ob + 2 * PLANE4 + oidx, v);                      // HL

    v.x = 0.5f * (td0 - bd0); v.y = 0.5f * (td1 - bd1);
    v.z = 0.5f * (td2 - bd2); v.w = 0.5f * (td3 - bd3);
    __stcs(ob + 3 * PLANE4 + oidx, v);                      // HH
}

// block (32, 8): one warp per 2 output rows -> 16 rows/block. grid: (H/16, B*C)
__global__ __launch_bounds__(256)
void haar_dwt_kernel(const float* __restrict__ x, float* __restrict__ out)
{
    const int lane = threadIdx.x;                     // 0..31
    const int h0   = blockIdx.x * 16 + threadIdx.y * 2;   // first output row
    const int bc   = blockIdx.y;

    const float4* xp4 = (const float4*)(x + (size_t)bc * DWT_H * DWT_W);
    const float4* r0  = xp4 + h0 * W4;

    // ---- front-batched loads: 6 independent 512B/warp LDG.128 (MLP=6) ----
    float4 t1 = r0[lane];                 // row h0,   cols [0,128)
    float4 t2 = r0[lane + 32];            // row h0,   cols [128,256)
    float4 m1 = r0[W4 + lane];            // row h0+1  (h0+1 <= 255 always)
    float4 m2 = r0[W4 + lane + 32];
    float4 b1, b2;
    if (h0 + 2 < DWT_H) {
        b1 = r0[2 * W4 + lane];           // row h0+2
        b2 = r0[2 * W4 + lane + 32];
    } else {
        b1 = make_float4(0.f, 0.f, 0.f, 0.f);
        b2 = b1;
    }

    // ---- horizontal neighbors via shuffle ----
    float nt1 = __shfl_down_sync(FULL, t1.x, 1);
    float nt2 = __shfl_down_sync(FULL, t2.x, 1);
    float nm1 = __shfl_down_sync(FULL, m1.x, 1);
    float nm2 = __shfl_down_sync(FULL, m2.x, 1);
    float nb1 = __shfl_down_sync(FULL, b1.x, 1);
    float nb2 = __shfl_down_sync(FULL, b2.x, 1);
    const float t2x0 = __shfl_sync(FULL, t2.x, 0);   // col 128 values
    const float m2x0 = __shfl_sync(FULL, m2.x, 0);
    const float b2x0 = __shfl_sync(FULL, b2.x, 0);
    if (lane == 31) {
        nt1 = t2x0;  nm1 = m2x0;  nb1 = b2x0;   // group1 lane31 -> col 128
        nt2 = 0.f;   nm2 = 0.f;   nb2 = 0.f;    // col 256 -> zero pad
    }

    float4* ob = (float4*)out + (size_t)(4 * bc) * PLANE4;
    const size_t oA = (size_t)h0 * W4 + lane;        // output row h0
    const size_t oB = oA + W4;                       // output row h0+1

    // output row h0: (top=row h0, bottom=row h0+1)
    subbands_store(ob, oA,      t1, m1, nt1, nm1);
    subbands_store(ob, oA + 32, t2, m2, nt2, nm2);
    // output row h0+1: (top=row h0+1, bottom=row h0+2)
    subbands_store(ob, oB,      m1, b1, nm1, nb1);
    subbands_store(ob, oB + 32, m2, b2, nm2, nb2);
}

extern "C" void kernel_launch(void* const* d_in, const int* in_sizes, int n_in,
                              void* d_out, int out_size)
{
    const float* x = (const float*)d_in[0];
    float* out = (float*)d_out;

    const int n_planes = in_sizes[0] / (DWT_H * DWT_W);   // B*C = 512

    dim3 block(32, 8, 1);
    dim3 grid(DWT_H / 16, n_planes, 1);
    haar_dwt_kernel<<<grid, block>>>(x, out);
}